// round 13
// baseline (speedup 1.0000x reference)
#include <cuda_runtime.h>
#include <cuda_fp16.h>
#include <stdint.h>
#include <math.h>

// Problem constants
#define B_   4
#define T_   2048
#define DM_  1024
#define H_   16
#define DH_  64
#define M_   (B_ * T_)
#define NW_  (DM_ * DM_)

// Scratch (device globals: allocation-free rule)
__device__ __half g_xh[M_ * DM_];        // fp16 x
__device__ __half g_wh[4 * NW_];         // fp16 Wq,Wk,Wv,Wo
__device__ __half g_q[M_ * DM_];         // [B,H,T,DH], pre-scaled by 1/8
__device__ __half g_k[M_ * DM_];
__device__ __half g_v[M_ * DM_];
__device__ __half g_y[M_ * DM_];         // attention out, [B,T,DM]

// ---------------------------------------------------------------------------
// Helpers
// ---------------------------------------------------------------------------
__device__ __forceinline__ uint32_t smem_u32(const void* p) {
    uint32_t a;
    asm("{ .reg .u64 t; cvta.to.shared.u64 t, %1; cvt.u32.u64 %0, t; }"
        : "=r"(a) : "l"(p));
    return a;
}

__device__ __forceinline__ const char* to_global(const void* p) {
    uint64_t g;
    asm("cvta.to.global.u64 %0, %1;" : "=l"(g) : "l"(p));
    return (const char*)g;
}

__device__ __forceinline__ void mma_f16_16x8x16(
    float* c, const uint32_t* a, uint32_t b0, uint32_t b1)
{
    asm volatile(
        "mma.sync.aligned.m16n8k16.row.col.f32.f16.f16.f32 "
        "{%0,%1,%2,%3}, {%4,%5,%6,%7}, {%8,%9}, {%0,%1,%2,%3};"
        : "+f"(c[0]), "+f"(c[1]), "+f"(c[2]), "+f"(c[3])
        : "r"(a[0]), "r"(a[1]), "r"(a[2]), "r"(a[3]), "r"(b0), "r"(b1));
}

#define LDSM_X4(r0, r1, r2, r3, a) \
    asm volatile("ldmatrix.sync.aligned.m8n8.x4.shared.b16 {%0,%1,%2,%3}, [%4];" \
                 : "=r"(r0), "=r"(r1), "=r"(r2), "=r"(r3) : "r"(a))
#define LDSM_X4T(r0, r1, r2, r3, a) \
    asm volatile("ldmatrix.sync.aligned.m8n8.x4.trans.shared.b16 {%0,%1,%2,%3}, [%4];" \
                 : "=r"(r0), "=r"(r1), "=r"(r2), "=r"(r3) : "r"(a))
#define CP16(dst, src) \
    asm volatile("cp.async.cg.shared.global [%0], [%1], 16;" :: "r"(dst), "l"(src) : "memory")
#define CP_COMMIT() asm volatile("cp.async.commit_group;" ::: "memory")
#define CP_WAIT1()  asm volatile("cp.async.wait_group 1;" ::: "memory")

__device__ __forceinline__ uint32_t packh2(float a, float b) {
    __half2 h = __floats2half2_rn(a, b);
    return *(uint32_t*)&h;
}

// ---------------------------------------------------------------------------
// Fused fp32 -> fp16 conversion (x + all 4 weights in one launch)
// ---------------------------------------------------------------------------
__global__ void __launch_bounds__(256) f2h_all(
    const float4* __restrict__ x,  const float4* __restrict__ wq,
    const float4* __restrict__ wk, const float4* __restrict__ wv,
    const float4* __restrict__ wo, __half2* __restrict__ xh,
    __half2* __restrict__ wh)
{
    int i = blockIdx.x * 256 + threadIdx.x;
    const float4* src;
    __half2* dst;
    if (i < 2097152) {                       // x: 8M floats = 2M float4
        src = x + i;
        dst = xh + 2 * (size_t)i;
    } else {
        int j = i - 2097152;                 // weights: 4 x 256K float4
        int w = j >> 18, off = j & 0x3FFFF;
        const float4* ws = (w == 0) ? wq : (w == 1) ? wk : (w == 2) ? wv : wo;
        src = ws + off;
        dst = wh + (size_t)w * 524288 + 2 * (size_t)off;
    }
    float4 v = *src;
    dst[0] = __floats2half2_rn(v.x, v.y);
    dst[1] = __floats2half2_rn(v.z, v.w);
}

// ---------------------------------------------------------------------------
// fp16 mma GEMM core: C[M,N] = (A[M,K] @ W[N,K]^T + bias[N]) * scale
// CTA tile 128x128, 512 threads = 16 warps (4m x 4n), warp tile 32x32.
// Low regs/warp -> 2 CTAs/SM = 32 warps/SM (2x R11 occupancy).
// BK=64, 3-stage cp.async. 144B SMEM rows -> ldmatrix conflict-free.
// ---------------------------------------------------------------------------
#define MATB  (128 * 144)                // 18432 B per padded 128x64 half tile
#define STGB  (2 * MATB)                 // A + W per stage = 36864 B
#define GSMEM (3 * STGB)                 // 110592 B

__device__ __forceinline__ void load_stage_h(
    const __half* __restrict__ A, const __half* __restrict__ W,
    int m0, int n0, int chunk, uint32_t sbase, int tid)
{
    const uint32_t st = sbase + (uint32_t)(chunk % 3) * STGB;
#pragma unroll
    for (int j = 0; j < 2; j++) {
        int idx = tid + j * 512;             // 0..1023
        int row = idx >> 3;                  // 0..127
        int ch  = idx & 7;                   // 16B chunk in 128B row
        uint32_t dst = st + (uint32_t)(row * 144 + ch * 16);
        CP16(dst, to_global(A + (size_t)(m0 + row) * DM_ + chunk * 64) + ch * 16);
        CP16(dst + MATB, to_global(W + (size_t)(n0 + row) * DM_ + chunk * 64) + ch * 16);
    }
}

__device__ __forceinline__ void gemm_core(
    const __half* __restrict__ A, const __half* __restrict__ W,
    const float* __restrict__ bias, float* __restrict__ Cf,
    __half* __restrict__ Ch, float scale, int qkv_layout, char* smraw)
{
    const uint32_t sbase = smem_u32(smraw);
    const int tid  = threadIdx.x;
    const int wid  = tid >> 5;
    const int lane = tid & 31;
    const int g    = lane >> 2;
    const int tg   = lane & 3;
    const int m0 = blockIdx.y * 128;
    const int n0 = blockIdx.x * 128;
    const int m_w = (wid >> 2) * 32;       // 4 warp rows
    const int n_w = (wid & 3) * 32;        // 4 warp cols

    float acc[2][4][4];
#pragma unroll
    for (int i = 0; i < 2; i++)
#pragma unroll
        for (int j = 0; j < 4; j++)
#pragma unroll
            for (int r = 0; r < 4; r++) acc[i][j][r] = 0.0f;

    load_stage_h(A, W, m0, n0, 0, sbase, tid); CP_COMMIT();
    load_stage_h(A, W, m0, n0, 1, sbase, tid); CP_COMMIT();

    // lane-dependent ldmatrix offsets (within a stage)
    const uint32_t a_off = (uint32_t)(m_w + (lane & 15)) * 144 + (uint32_t)(lane >> 4) * 16;
    const uint32_t b_off = (uint32_t)MATB
                         + (uint32_t)(n_w + (lane & 7) + (lane >> 4) * 8) * 144
                         + (uint32_t)((lane >> 3) & 1) * 16;

    for (int i = 0; i < 16; i++) {
        CP_WAIT1();
        __syncthreads();
        if (i + 2 < 16) load_stage_h(A, W, m0, n0, i + 2, sbase, tid);
        CP_COMMIT();

        const uint32_t ss = sbase + (uint32_t)(i % 3) * STGB;
#pragma unroll
        for (int ks = 0; ks < 4; ks++) {
            const uint32_t ko = (uint32_t)(ks * 32);
            uint32_t af[2][4];
#pragma unroll
            for (int ma = 0; ma < 2; ma++) {
                uint32_t addr = ss + a_off + (uint32_t)(ma * 16) * 144 + ko;
                LDSM_X4(af[ma][0], af[ma][1], af[ma][2], af[ma][3], addr);
            }
#pragma unroll
            for (int nb = 0; nb < 2; nb++) {
                uint32_t b0, b1, b2, b3;
                uint32_t addr = ss + b_off + (uint32_t)(nb * 16) * 144 + ko;
                LDSM_X4(b0, b1, b2, b3, addr);
#pragma unroll
                for (int ma = 0; ma < 2; ma++) {
                    mma_f16_16x8x16(acc[ma][2 * nb],     af[ma], b0, b1);
                    mma_f16_16x8x16(acc[ma][2 * nb + 1], af[ma], b2, b3);
                }
            }
        }
    }

    // epilogue: regs -> global
#pragma unroll
    for (int ma = 0; ma < 2; ma++) {
        const int mA = m0 + m_w + ma * 16 + g;
#pragma unroll
        for (int na = 0; na < 4; na++) {
            const int n = n0 + n_w + na * 8 + tg * 2;
            const float b0 = bias[n], b1 = bias[n + 1];
#pragma unroll
            for (int half_i = 0; half_i < 2; half_i++) {
                const int m = mA + half_i * 8;
                float v0 = (acc[ma][na][half_i * 2 + 0] + b0) * scale;
                float v1 = (acc[ma][na][half_i * 2 + 1] + b1) * scale;
                if (qkv_layout) {
                    const int b = m >> 11;
                    const int t = m & (T_ - 1);
                    const int h = n >> 6;
                    const int d = n & (DH_ - 1);
                    *(__half2*)&Ch[(((size_t)(b * H_ + h) * T_) + t) * DH_ + d] =
                        __floats2half2_rn(v0, v1);
                } else {
                    float2 v; v.x = v0; v.y = v1;
                    *(float2*)&Cf[(size_t)m * DM_ + n] = v;
                }
            }
        }
    }
}

// Fused QKV projection: grid.z selects Q/K/V
__global__ void __launch_bounds__(512, 2) hgemm_qkv_kernel(
    const __half* __restrict__ A, const __half* __restrict__ Wbase,
    const float* __restrict__ bq, const float* __restrict__ bk,
    const float* __restrict__ bv,
    __half* __restrict__ oq, __half* __restrict__ ok, __half* __restrict__ ov)
{
    extern __shared__ char smraw[];
    const int z = blockIdx.z;
    const __half* W = Wbase + (size_t)z * NW_;
    const float* bias = (z == 0) ? bq : (z == 1) ? bk : bv;
    __half* Ch = (z == 0) ? oq : (z == 1) ? ok : ov;
    const float scale = (z == 0) ? 0.125f : 1.0f;
    gemm_core(A, W, bias, nullptr, Ch, scale, 1, smraw);
}

// Output projection (fp32 out)
__global__ void __launch_bounds__(512, 2) hgemm_out_kernel(
    const __half* __restrict__ A, const __half* __restrict__ W,
    const float* __restrict__ bias, float* __restrict__ Cf)
{
    extern __shared__ char smraw[];
    gemm_core(A, W, bias, Cf, nullptr, 1.0f, 0, smraw);
}

// ---------------------------------------------------------------------------
// Tensor-core flash attention (unchanged from R11).
// ---------------------------------------------------------------------------
#define AKROW  144
#define KTILE  (64 * AKROW)
#define ASTG   (2 * KTILE)
#define ASMEM  (3 * ASTG)

__device__ __forceinline__ void load_kv(size_t base, int c, uint32_t st, int tid)
{
#pragma unroll
    for (int j = 0; j < 2; j++) {
        int idx = tid + j * 256;
        int row = idx >> 3, ch = idx & 7;
        uint32_t dst = st + (uint32_t)(row * AKROW + ch * 16);
        CP16(dst,         to_global(g_k + base + (size_t)(c + row) * DH_) + ch * 16);
        CP16(dst + KTILE, to_global(g_v + base + (size_t)(c + row) * DH_) + ch * 16);
    }
}

__global__ void __launch_bounds__(256, 2) attn_kernel()
{
    extern __shared__ char ash[];
    const uint32_t abase = smem_u32(ash);

    const int tid  = threadIdx.x;
    const int w    = tid >> 5;
    const int lane = tid & 31;
    const int g    = lane >> 2;
    const int tg   = lane & 3;
    const int b  = blockIdx.z;
    const int h  = blockIdx.y;
    const int qb = (gridDim.x - 1) - blockIdx.x;
    const int W0 = qb * 128 + w * 16;

    const size_t base = ((size_t)(b * H_ + h)) * T_ * DH_;

    uint32_t aq[4][4];
    {
        const uint32_t* Qg = (const uint32_t*)(g_q + base);
        const int r0 = (W0 + g) * 32;
        const int r1 = (W0 + g + 8) * 32;
#pragma unroll
        for (int ks = 0; ks < 4; ks++) {
            const int o = ks * 8 + tg;
            aq[ks][0] = Qg[r0 + o];
            aq[ks][1] = Qg[r1 + o];
            aq[ks][2] = Qg[r0 + o + 4];
            aq[ks][3] = Qg[r1 + o + 4];
        }
    }

    float o[8][4];
#pragma unroll
    for (int i = 0; i < 8; i++)
#pragma unroll
        for (int r = 0; r < 4; r++) o[i][r] = 0.0f;
    float m0 = -1e30f, m1 = -1e30f, l0 = 0.0f, l1 = 0.0f;
    const unsigned FULL = 0xFFFFFFFFu;

    const uint32_t kb_row = (uint32_t)((lane & 7) + (lane >> 4) * 8);
    const uint32_t kb_k16 = (uint32_t)((lane >> 3) & 1) * 16;
    const uint32_t vb_row = (uint32_t)((lane & 7) + ((lane >> 3) & 1) * 8);
    const uint32_t vb_d16 = (uint32_t)(lane >> 4) * 16;

    const int ntiles = 2 * qb + 2;
    load_kv(base, 0, abase, tid);            CP_COMMIT();
    load_kv(base, 64, abase + ASTG, tid);    CP_COMMIT();

    for (int t = 0; t < ntiles; t++) {
        CP_WAIT1();
        __syncthreads();
        if (t + 2 < ntiles)
            load_kv(base, (t + 2) * 64, abase + (uint32_t)((t + 2) % 3) * ASTG, tid);
        CP_COMMIT();

        const int c = t * 64;
        if (c <= W0 + 15) {
            const uint32_t kst = abase + (uint32_t)(t % 3) * ASTG;
            const uint32_t vst = kst + KTILE;

            float s[8][4];
#pragma unroll
            for (int i = 0; i < 8; i++)
#pragma unroll
                for (int r = 0; r < 4; r++) s[i][r] = 0.0f;
#pragma unroll
            for (int ks = 0; ks < 4; ks++) {
#pragma unroll
                for (int nb = 0; nb < 4; nb++) {
                    uint32_t b0, b1, b2, b3;
                    uint32_t addr = kst + (uint32_t)(nb * 16 + kb_row) * AKROW
                                  + ks * 32 + kb_k16;
                    LDSM_X4(b0, b1, b2, b3, addr);
                    mma_f16_16x8x16(s[2 * nb],     aq[ks], b0, b1);
                    mma_f16_16x8x16(s[2 * nb + 1], aq[ks], b2, b3);
                }
            }
            if (c + 63 > W0) {
#pragma unroll
                for (int na = 0; na < 8; na++) {
                    const int key0 = c + na * 8 + tg * 2;
                    if (key0 > W0 + g)          s[na][0] = -1e30f;
                    if (key0 + 1 > W0 + g)      s[na][1] = -1e30f;
                    if (key0 > W0 + g + 8)      s[na][2] = -1e30f;
                    if (key0 + 1 > W0 + g + 8)  s[na][3] = -1e30f;
                }
            }
            float mx0 = -1e30f, mx1 = -1e30f;
#pragma unroll
            for (int na = 0; na < 8; na++) {
                mx0 = fmaxf(mx0, fmaxf(s[na][0], s[na][1]));
                mx1 = fmaxf(mx1, fmaxf(s[na][2], s[na][3]));
            }
            mx0 = fmaxf(mx0, __shfl_xor_sync(FULL, mx0, 1));
            mx0 = fmaxf(mx0, __shfl_xor_sync(FULL, mx0, 2));
            mx1 = fmaxf(mx1, __shfl_xor_sync(FULL, mx1, 1));
            mx1 = fmaxf(mx1, __shfl_xor_sync(FULL, mx1, 2));
            const float mn0 = fmaxf(m0, mx0);
            const float mn1 = fmaxf(m1, mx1);
            const float cor0 = __expf(m0 - mn0);
            const float cor1 = __expf(m1 - mn1);
            float sum0 = 0.0f, sum1 = 0.0f;
#pragma unroll
            for (int na = 0; na < 8; na++) {
                s[na][0] = __expf(s[na][0] - mn0);
                s[na][1] = __expf(s[na][1] - mn0);
                s[na][2] = __expf(s[na][2] - mn1);
                s[na][3] = __expf(s[na][3] - mn1);
                sum0 += s[na][0] + s[na][1];
                sum1 += s[na][2] + s[na][3];
            }
            sum0 += __shfl_xor_sync(FULL, sum0, 1);
            sum0 += __shfl_xor_sync(FULL, sum0, 2);
            sum1 += __shfl_xor_sync(FULL, sum1, 1);
            sum1 += __shfl_xor_sync(FULL, sum1, 2);
            l0 = l0 * cor0 + sum0;
            l1 = l1 * cor1 + sum1;
#pragma unroll
            for (int na = 0; na < 8; na++) {
                o[na][0] *= cor0; o[na][1] *= cor0;
                o[na][2] *= cor1; o[na][3] *= cor1;
            }
            m0 = mn0; m1 = mn1;

#pragma unroll
            for (int ks2 = 0; ks2 < 4; ks2++) {
                uint32_t pa[4];
                pa[0] = packh2(s[2 * ks2][0],     s[2 * ks2][1]);
                pa[1] = packh2(s[2 * ks2][2],     s[2 * ks2][3]);
                pa[2] = packh2(s[2 * ks2 + 1][0], s[2 * ks2 + 1][1]);
                pa[3] = packh2(s[2 * ks2 + 1][2], s[2 * ks2 + 1][3]);
#pragma unroll
                for (int nb = 0; nb < 4; nb++) {
                    uint32_t b0, b1, b2, b3;
                    uint32_t addr = vst + (uint32_t)(ks2 * 16 + vb_row) * AKROW
                                  + (uint32_t)(nb * 16) * 2 + vb_d16;
                    LDSM_X4T(b0, b1, b2, b3, addr);
                    mma_f16_16x8x16(o[2 * nb],     pa, b0, b1);
                    mma_f16_16x8x16(o[2 * nb + 1], pa, b2, b3);
                }
            }
        }
    }

    const float inv0 = 1.0f / l0;
    const float inv1 = 1.0f / l1;
    const int q0 = W0 + g;
    const int q1 = W0 + g + 8;
    __half* y0 = g_y + ((size_t)(b * T_ + q0)) * DM_ + h * DH_;
    __half* y1 = g_y + ((size_t)(b * T_ + q1)) * DM_ + h * DH_;
#pragma unroll
    for (int na = 0; na < 8; na++) {
        const int d = na * 8 + tg * 2;
        *(__half2*)&y0[d] = __floats2half2_rn(o[na][0] * inv0, o[na][1] * inv0);
        *(__half2*)&y1[d] = __floats2half2_rn(o[na][2] * inv1, o[na][3] * inv1);
    }
}

// ---------------------------------------------------------------------------
// Launch
// ---------------------------------------------------------------------------
extern "C" void kernel_launch(void* const* d_in, const int* in_sizes, int n_in,
                              void* d_out, int out_size)
{
    const float* x  = (const float*)d_in[0];
    const float* Wq = (const float*)d_in[1];
    const float* bq = (const float*)d_in[2];
    const float* Wk = (const float*)d_in[3];
    const float* bk = (const float*)d_in[4];
    const float* Wv = (const float*)d_in[5];
    const float* bv = (const float*)d_in[6];
    const float* Wo = (const float*)d_in[7];
    const float* bo = (const float*)d_in[8];
    float* out = (float*)d_out;

    __half *pxh, *pwh, *pq, *pk, *pv, *py;
    cudaGetSymbolAddress((void**)&pxh, g_xh);
    cudaGetSymbolAddress((void**)&pwh, g_wh);
    cudaGetSymbolAddress((void**)&pq, g_q);
    cudaGetSymbolAddress((void**)&pk, g_k);
    cudaGetSymbolAddress((void**)&pv, g_v);
    cudaGetSymbolAddress((void**)&py, g_y);

    static int attr_set = 0;
    if (!attr_set) {
        cudaFuncSetAttribute(hgemm_qkv_kernel,
                             cudaFuncAttributeMaxDynamicSharedMemorySize, GSMEM);
        cudaFuncSetAttribute(hgemm_out_kernel,
                             cudaFuncAttributeMaxDynamicSharedMemorySize, GSMEM);
        cudaFuncSetAttribute(attn_kernel,
                             cudaFuncAttributeMaxDynamicSharedMemorySize, ASMEM);
        attr_set = 1;
    }

    f2h_all<<<12288, 256>>>((const float4*)x, (const float4*)Wq, (const float4*)Wk,
                            (const float4*)Wv, (const float4*)Wo,
                            (__half2*)pxh, (__half2*)pwh);

    dim3 qgrid(DM_ / 128, M_ / 128, 3);  // (8, 64, 3)
    hgemm_qkv_kernel<<<qgrid, 512, GSMEM>>>(pxh, pwh, bq, bk, bv, pq, pk, pv);

    dim3 agrid(T_ / 128, H_, B_);        // (16, 16, 4)
    attn_kernel<<<agrid, 256, ASMEM>>>();

    dim3 ggrid(DM_ / 128, M_ / 128);     // (8, 64)
    hgemm_out_kernel<<<ggrid, 512, GSMEM>>>(py, pwh + 3 * (size_t)NW_, bo, out);
}